// round 9
// baseline (speedup 1.0000x reference)
#include <cuda_runtime.h>
#include <cuda_bf16.h>
#include <math.h>
#include <cstdint>

#define Bc 64
#define Tt 197
#define Dd 768
#define Hh 12
#define DKk 64
#define Mrows (Bc * Tt)   // 12608

typedef unsigned long long u64;

// ===== f32x2 helpers =====
__device__ __forceinline__ u64 pk2(float lo, float hi) {
    u64 r; asm("mov.b64 %0,{%1,%2};" : "=l"(r) : "f"(lo), "f"(hi)); return r;
}
__device__ __forceinline__ float2 upk2(u64 v) {
    float2 f; asm("mov.b64 {%0,%1},%2;" : "=f"(f.x), "=f"(f.y) : "l"(v)); return f;
}
__device__ __forceinline__ void ffma2(u64 &c, u64 a, u64 b) {
    asm("fma.rn.f32x2 %0,%1,%2,%0;" : "+l"(c) : "l"(a), "l"(b));
}

// ===== tf32 / mma.sync helpers =====
__device__ __forceinline__ uint32_t smem_u32(const void* p) {
    uint32_t a;
    asm("{ .reg .u64 t; cvta.to.shared.u64 t, %1; cvt.u32.u64 %0, t; }" : "=r"(a) : "l"(p));
    return a;
}
__device__ __forceinline__ float tf32r(float v) {
    uint32_t h;
    asm("cvt.rna.tf32.f32 %0, %1;" : "=r"(h) : "f"(v));
    return __uint_as_float(h);
}
__device__ __forceinline__ void ldsm4(uint32_t* r, uint32_t addr) {
    asm volatile("ldmatrix.sync.aligned.m8n8.x4.shared.b16 {%0,%1,%2,%3}, [%4];"
                 : "=r"(r[0]), "=r"(r[1]), "=r"(r[2]), "=r"(r[3]) : "r"(addr));
}
__device__ __forceinline__ void mma8(float* d, const uint32_t* a, uint32_t b0, uint32_t b1) {
    asm volatile(
        "mma.sync.aligned.m16n8k8.row.col.f32.tf32.tf32.f32 "
        "{%0,%1,%2,%3},{%4,%5,%6,%7},{%8,%9},{%0,%1,%2,%3};"
        : "+f"(d[0]), "+f"(d[1]), "+f"(d[2]), "+f"(d[3])
        : "r"(a[0]), "r"(a[1]), "r"(a[2]), "r"(a[3]), "r"(b0), "r"(b1));
}

// ===== scratch =====
__device__ float g_q[Bc * Hh * Tt * DKk];
__device__ float g_k[Bc * Hh * Tt * DKk];
__device__ float g_v[Bc * Hh * Tt * DKk];
__device__ float g_ctx[Bc * Tt * Dd];

// ---------------------------------------------------------------------------
// R4-proven FFMA2 GEMM (exact fp32) for Q/K projections.
// 128x128 tile, KT=16, register prefetch. mode 0 head-split write.
// ---------------------------------------------------------------------------
#define KT 16

__device__ __forceinline__ void gemm_core(
    const float* __restrict__ A, const float* __restrict__ W,
    const float* __restrict__ bias, float* __restrict__ out,
    float* As, float* Ws)
{
    const int tid = threadIdx.x;
    const int tx = tid & 15;
    const int ty = tid >> 4;
    const int m0 = blockIdx.y * 128;
    const int n0 = blockIdx.x * 128;

    u64 c2[4][8];
#pragma unroll
    for (int i = 0; i < 4; i++)
#pragma unroll
        for (int j = 0; j < 8; j++) c2[i][j] = 0ull;

    const int ar = tid >> 1;
    const int ah = tid & 1;
    const int wk = tid >> 5;
    const int wc = tid & 31;

    float4 a0, a1, w0, w1;
    {
        a0 = make_float4(0.f, 0.f, 0.f, 0.f); a1 = a0;
        if (m0 + ar < Mrows) {
            const float* Ap = A + (size_t)(m0 + ar) * Dd + ah * 8;
            a0 = *(const float4*)Ap;
            a1 = *(const float4*)(Ap + 4);
        }
        const float* Wp = W + (size_t)wk * Dd + n0 + wc * 4;
        w0 = *(const float4*)Wp;
        w1 = *(const float4*)(Wp + 8 * Dd);
    }

    for (int k0 = 0; k0 < Dd; k0 += KT) {
        __syncthreads();
        As[(ah * 8 + 0) * 128 + ar] = a0.x; As[(ah * 8 + 1) * 128 + ar] = a0.y;
        As[(ah * 8 + 2) * 128 + ar] = a0.z; As[(ah * 8 + 3) * 128 + ar] = a0.w;
        As[(ah * 8 + 4) * 128 + ar] = a1.x; As[(ah * 8 + 5) * 128 + ar] = a1.y;
        As[(ah * 8 + 6) * 128 + ar] = a1.z; As[(ah * 8 + 7) * 128 + ar] = a1.w;
        *(float4*)&Ws[wk * 128 + wc * 4]       = w0;
        *(float4*)&Ws[(wk + 8) * 128 + wc * 4] = w1;
        __syncthreads();

        if (k0 + KT < Dd) {
            a0 = make_float4(0.f, 0.f, 0.f, 0.f); a1 = a0;
            if (m0 + ar < Mrows) {
                const float* Ap = A + (size_t)(m0 + ar) * Dd + (k0 + KT) + ah * 8;
                a0 = *(const float4*)Ap;
                a1 = *(const float4*)(Ap + 4);
            }
            const float* Wp = W + (size_t)(k0 + KT + wk) * Dd + n0 + wc * 4;
            w0 = *(const float4*)Wp;
            w1 = *(const float4*)(Wp + 8 * Dd);
        }

#pragma unroll
        for (int kk = 0; kk < KT; kk++) {
            const float* Ak = As + kk * 128;
            const float* Wr = Ws + kk * 128;
            u64 ap[4];
            ap[0] = *(const u64*)&Ak[ty * 4];
            ap[1] = *(const u64*)&Ak[ty * 4 + 2];
            ap[2] = *(const u64*)&Ak[64 + ty * 4];
            ap[3] = *(const u64*)&Ak[64 + ty * 4 + 2];
            float4 bv0 = *(const float4*)&Wr[tx * 4];
            float4 bv1 = *(const float4*)&Wr[64 + tx * 4];
            u64 bd[8];
            bd[0] = pk2(bv0.x, bv0.x); bd[1] = pk2(bv0.y, bv0.y);
            bd[2] = pk2(bv0.z, bv0.z); bd[3] = pk2(bv0.w, bv0.w);
            bd[4] = pk2(bv1.x, bv1.x); bd[5] = pk2(bv1.y, bv1.y);
            bd[6] = pk2(bv1.z, bv1.z); bd[7] = pk2(bv1.w, bv1.w);
#pragma unroll
            for (int i = 0; i < 4; i++)
#pragma unroll
                for (int j = 0; j < 8; j++) ffma2(c2[i][j], ap[i], bd[j]);
        }
    }

#pragma unroll
    for (int i = 0; i < 4; i++) {
        int rbase = m0 + ((i < 2) ? (ty * 4 + i * 2) : (64 + ty * 4 + (i - 2) * 2));
#pragma unroll
        for (int j = 0; j < 8; j++) {
            int cidx = n0 + ((j < 4) ? (tx * 4 + j) : (64 + tx * 4 + (j - 4)));
            float2 f = upk2(c2[i][j]);
            float bia = bias[cidx];
            f.x += bia; f.y += bia;
#pragma unroll
            for (int s = 0; s < 2; s++) {
                int r = rbase + s;
                if (r >= Mrows) continue;
                float v = s ? f.y : f.x;
                int bi = r / Tt, t = r - (r / Tt) * Tt;
                int h = cidx >> 6, dk = cidx & 63;
                out[(((size_t)(bi * Hh + h)) * Tt + t) * DKk + dk] = v;
            }
        }
    }
}

__global__ void __launch_bounds__(256, 2) qk_kernel(
    const float* __restrict__ x,
    const float* __restrict__ Wq, const float* __restrict__ Wk2,
    const float* __restrict__ bq, const float* __restrict__ bk2,
    float* __restrict__ q, float* __restrict__ k)
{
    __shared__ float As[KT * 128];
    __shared__ float Ws[KT * 128];
    int z = blockIdx.z;
    gemm_core(x, z ? Wk2 : Wq, z ? bk2 : bq, z ? k : q, As, Ws);
}

// ---------------------------------------------------------------------------
// 2-limb 3-product TF32 mma.sync GEMM (V, O projections — smooth paths).
// CTA 256(m) x 128(n), 8 warps, warp tile 64x64, SA=36.
// ---------------------------------------------------------------------------
#define SA 36
#define GEMM_SMEM_TF ((256 + 128) * SA * 4)   // 55296

__global__ void __launch_bounds__(256) tf32_gemm_kernel(
    const float* __restrict__ A, const float* __restrict__ W,
    const float* __restrict__ bias, float* __restrict__ out, int mode)
{
    extern __shared__ float smf[];
    float* As = smf;              // [256][SA]
    float* Ws = smf + 256 * SA;   // [128][SA]
    const uint32_t Asu = smem_u32(As);
    const uint32_t Wsu = smem_u32(Ws);

    const int tid  = threadIdx.x;
    const int lane = tid & 31;
    const int wid  = tid >> 5;
    const int wm   = wid >> 1;
    const int wn   = wid & 1;
    const int m0   = blockIdx.y * 256;
    const int n0   = blockIdx.x * 128;

    const int wk = tid >> 5;
    const int wc = tid & 31;

    float d[4][8][4];
#pragma unroll
    for (int mf = 0; mf < 4; mf++)
#pragma unroll
        for (int nf = 0; nf < 8; nf++)
#pragma unroll
            for (int i = 0; i < 4; i++) d[mf][nf][i] = 0.f;

    const int a_row = wm * 64 + (lane & 15);
    const int a_co  = (lane >> 4) << 2;
    const int b_row = wn * 64 + ((lane >> 4) << 3) + (lane & 7);
    const int b_co  = ((lane >> 3) & 1) << 2;

    float4 pa[4], pw[2];

    {
        const int r = m0 + tid;
        if (r < Mrows) {
            const float* Ap = A + (size_t)r * Dd;
#pragma unroll
            for (int i = 0; i < 4; i++) pa[i] = *(const float4*)(Ap + i * 4);
        } else {
#pragma unroll
            for (int i = 0; i < 4; i++) pa[i] = make_float4(0.f, 0.f, 0.f, 0.f);
        }
        const float* Wp = W + (size_t)wk * Dd + n0 + wc * 4;
        pw[0] = *(const float4*)Wp;
        pw[1] = *(const float4*)(Wp + 8 * Dd);
    }

    for (int c = 0; c < Dd / 16; c++) {
        __syncthreads();
#pragma unroll
        for (int i = 0; i < 4; i++) {
            float vv[4] = {pa[i].x, pa[i].y, pa[i].z, pa[i].w};
            float h[4], m[4];
#pragma unroll
            for (int j = 0; j < 4; j++) {
                h[j] = tf32r(vv[j]);
                m[j] = tf32r(vv[j] - h[j]);
            }
            *(float4*)&As[tid * SA + i * 4]      = make_float4(h[0], h[1], h[2], h[3]);
            *(float4*)&As[tid * SA + 16 + i * 4] = make_float4(m[0], m[1], m[2], m[3]);
        }
#pragma unroll
        for (int p = 0; p < 2; p++) {
            float vj[4] = {p ? pw[1].x : pw[0].x, p ? pw[1].y : pw[0].y,
                           p ? pw[1].z : pw[0].z, p ? pw[1].w : pw[0].w};
            const int kq = wk + 8 * p;
#pragma unroll
            for (int j = 0; j < 4; j++) {
                const int n = wc * 4 + j;
                float h = tf32r(vj[j]);
                Ws[n * SA + kq]      = h;
                Ws[n * SA + 16 + kq] = tf32r(vj[j] - h);
            }
        }
        __syncthreads();

        if (c + 1 < Dd / 16) {
            const int r = m0 + tid;
            if (r < Mrows) {
                const float* Ap = A + (size_t)r * Dd + (c + 1) * 16;
#pragma unroll
                for (int i = 0; i < 4; i++) pa[i] = *(const float4*)(Ap + i * 4);
            } else {
#pragma unroll
                for (int i = 0; i < 4; i++) pa[i] = make_float4(0.f, 0.f, 0.f, 0.f);
            }
            const float* Wp = W + (size_t)((c + 1) * 16 + wk) * Dd + n0 + wc * 4;
            pw[0] = *(const float4*)Wp;
            pw[1] = *(const float4*)(Wp + 8 * Dd);
        }

        // products {hh, hm, mh}
#pragma unroll
        for (int s = 0; s < 3; s++) {
            const int ak0 = (s == 2) ? 16 : 0;
            const int bk0 = (s == 1) ? 16 : 0;
#pragma unroll
            for (int kk = 0; kk < 16; kk += 8) {
                const int akb = ak0 + kk, bkb = bk0 + kk;
                uint32_t a[4][4], b[4][4];
#pragma unroll
                for (int mf = 0; mf < 4; mf++)
                    ldsm4(a[mf], Asu + (uint32_t)(((a_row + mf * 16) * SA) + akb + a_co) * 4u);
#pragma unroll
                for (int g = 0; g < 4; g++)
                    ldsm4(b[g], Wsu + (uint32_t)(((b_row + g * 16) * SA) + bkb + b_co) * 4u);
#pragma unroll
                for (int mf = 0; mf < 4; mf++)
#pragma unroll
                    for (int nf = 0; nf < 8; nf++)
                        mma8(d[mf][nf], a[mf], b[nf >> 1][(nf & 1) * 2], b[nf >> 1][(nf & 1) * 2 + 1]);
            }
        }
    }

    const int gid = lane >> 2, tig = lane & 3;
#pragma unroll
    for (int mf = 0; mf < 4; mf++) {
        const int r0 = m0 + wm * 64 + mf * 16 + gid;
        const int r1 = r0 + 8;
        int bi0 = 0, t0 = 0, bi1 = 0, t1 = 0;
        const bool v0 = (r0 < Mrows), v1 = (r1 < Mrows);
        if (v0) { bi0 = r0 / Tt; t0 = r0 - bi0 * Tt; }
        if (v1) { bi1 = r1 / Tt; t1 = r1 - bi1 * Tt; }
#pragma unroll
        for (int nf = 0; nf < 8; nf++) {
            const int cg = n0 + wn * 64 + nf * 8 + tig * 2;
            const float bx = bias[cg], by = bias[cg + 1];
            float2 o0 = make_float2(d[mf][nf][0] + bx, d[mf][nf][1] + by);
            float2 o1 = make_float2(d[mf][nf][2] + bx, d[mf][nf][3] + by);
            if (mode == 0) {
                const int h = cg >> 6, dk = cg & 63;
                if (v0) *(float2*)&out[(((size_t)(bi0 * Hh + h)) * Tt + t0) * DKk + dk] = o0;
                if (v1) *(float2*)&out[(((size_t)(bi1 * Hh + h)) * Tt + t1) * DKk + dk] = o1;
            } else {
                if (v0) *(float2*)&out[(size_t)r0 * Dd + cg] = o0;
                if (v1) *(float2*)&out[(size_t)r1 * Dd + cg] = o1;
            }
        }
    }
}

// ---------------------------------------------------------------------------
// Attention (unchanged): per (b,h) CTA, 16 warps, 4 rows/warp, rotated smem.
// ---------------------------------------------------------------------------
#define NW 16
#define ATTN_SMEM ((2 * Tt * 64 + NW * 800) * 4)

__global__ void __launch_bounds__(32 * NW) attn3_kernel(
    const float* __restrict__ Q, const float* __restrict__ K,
    const float* __restrict__ V, float* __restrict__ ctx)
{
    extern __shared__ float sm[];
    float* Ks = sm;
    float* Vs = sm + Tt * 64;
    const int tid  = threadIdx.x;
    const int lane = tid & 31;
    const int w    = tid >> 5;
    float* Pg = sm + 2 * Tt * 64 + w * 800;

    const int bh = blockIdx.x;
    const int b  = bh / Hh;
    const int h  = bh - b * Hh;

    const float* Kb = K + (size_t)bh * Tt * DKk;
    const float* Vb = V + (size_t)bh * Tt * DKk;
    const float* Qb = Q + (size_t)bh * Tt * DKk;

    for (int e = tid; e < Tt * 32; e += 32 * NW) {
        int j = e >> 5, p = e & 31, c = 2 * p;
        int off = j * 64 + ((c + 2 * j) & 63);
        *(float2*)&Ks[off] = *(const float2*)&Kb[j * 64 + c];
        *(float2*)&Vs[off] = *(const float2*)&Vb[j * 64 + c];
    }
    __syncthreads();

    int jj[7], rot[7];
#pragma unroll
    for (int u = 0; u < 7; u++) {
        int j = lane + 32 * u;
        jj[u]  = (j > Tt - 1) ? (Tt - 1) : j;
        rot[u] = (2 * jj[u]) & 63;
    }
    const int myc = 2 * lane;

    for (int g = w; g < 50; g += NW) {
        const int r0 = g * 4;
        int rs[4];
#pragma unroll
        for (int s = 0; s < 4; s++) rs[s] = (r0 + s > Tt - 1) ? (Tt - 1) : (r0 + s);

        u64 acc[4][7];
#pragma unroll
        for (int s = 0; s < 4; s++)
#pragma unroll
            for (int u = 0; u < 7; u++) acc[s][u] = 0ull;

#pragma unroll
        for (int dc = 0; dc < 8; dc++) {
            u64 qp[4][4];
#pragma unroll
            for (int s = 0; s < 4; s++) {
                const float* qs = Qb + rs[s] * DKk + dc * 8;
                float4 qa = *(const float4*)qs;
                float4 qb = *(const float4*)(qs + 4);
                qp[s][0] = pk2(qa.x, qa.y); qp[s][1] = pk2(qa.z, qa.w);
                qp[s][2] = pk2(qb.x, qb.y); qp[s][3] = pk2(qb.z, qb.w);
            }
            const int c0 = dc * 8;
#pragma unroll
            for (int u = 0; u < 7; u++) {
                const float* kr = Ks + jj[u] * 64;
                u64 kp0 = *(const u64*)&kr[(c0 + 0 + rot[u]) & 63];
                u64 kp1 = *(const u64*)&kr[(c0 + 2 + rot[u]) & 63];
                u64 kp2 = *(const u64*)&kr[(c0 + 4 + rot[u]) & 63];
                u64 kp3 = *(const u64*)&kr[(c0 + 6 + rot[u]) & 63];
#pragma unroll
                for (int s = 0; s < 4; s++) {
                    ffma2(acc[s][u], qp[s][0], kp0);
                    ffma2(acc[s][u], qp[s][1], kp1);
                    ffma2(acc[s][u], qp[s][2], kp2);
                    ffma2(acc[s][u], qp[s][3], kp3);
                }
            }
        }

        float iv[4];
#pragma unroll
        for (int s = 0; s < 4; s++) {
            float sc[7];
            float mx = -1e30f;
#pragma unroll
            for (int u = 0; u < 7; u++) {
                float2 f = upk2(acc[s][u]);
                float val = floorf((f.x + f.y) * 0.125f);
                sc[u] = (lane + 32 * u < Tt) ? val : -1e30f;
                mx = fmaxf(mx, sc[u]);
            }
#pragma unroll
            for (int o = 16; o; o >>= 1) mx = fmaxf(mx, __shfl_xor_sync(0xffffffffu, mx, o));
            float sum = 0.f;
#pragma unroll
            for (int u = 0; u < 7; u++) {
                if (lane + 32 * u < Tt) {
                    float p = __expf(sc[u] - mx);
                    Pg[jj[u] * 4 + s] = p;
                    sum += p;
                }
            }
#pragma unroll
            for (int o = 16; o; o >>= 1) sum += __shfl_xor_sync(0xffffffffu, sum, o);
            iv[s] = 1.f / sum;
        }
        __syncwarp();

        u64 a[4] = {0ull, 0ull, 0ull, 0ull};
        for (int j = 0; j < Tt - 1; j += 2) {
            u64 v0 = *(const u64*)&Vs[j * 64 + ((myc + 2 * j) & 63)];
            u64 v1 = *(const u64*)&Vs[(j + 1) * 64 + ((myc + 2 * j + 2) & 63)];
            float4 pa = *(const float4*)&Pg[j * 4];
            float4 pb = *(const float4*)&Pg[j * 4 + 4];
            ffma2(a[0], pk2(pa.x, pa.x), v0); ffma2(a[0], pk2(pb.x, pb.x), v1);
            ffma2(a[1], pk2(pa.y, pa.y), v0); ffma2(a[1], pk2(pb.y, pb.y), v1);
            ffma2(a[2], pk2(pa.z, pa.z), v0); ffma2(a[2], pk2(pb.z, pb.z), v1);
            ffma2(a[3], pk2(pa.w, pa.w), v0); ffma2(a[3], pk2(pb.w, pb.w), v1);
        }
        {
            int j = Tt - 1;
            u64 v0 = *(const u64*)&Vs[j * 64 + ((myc + 2 * j) & 63)];
            float4 pa = *(const float4*)&Pg[j * 4];
            ffma2(a[0], pk2(pa.x, pa.x), v0);
            ffma2(a[1], pk2(pa.y, pa.y), v0);
            ffma2(a[2], pk2(pa.z, pa.z), v0);
            ffma2(a[3], pk2(pa.w, pa.w), v0);
        }

#pragma unroll
        for (int s = 0; s < 4; s++) {
            float2 o = upk2(a[s]);
            o.x *= iv[s]; o.y *= iv[s];
            *(float2*)&ctx[((size_t)(b * Tt + rs[s])) * Dd + h * DKk + myc] = o;
        }
        __syncwarp();
    }
}

// ---------------------------------------------------------------------------
extern "C" void kernel_launch(void* const* d_in, const int* in_sizes, int n_in,
                              void* d_out, int out_size)
{
    const float* x  = (const float*)d_in[0];
    const float* Wq = (const float*)d_in[1];
    const float* bq = (const float*)d_in[2];
    const float* Wk = (const float*)d_in[3];
    const float* bk = (const float*)d_in[4];
    const float* Wv = (const float*)d_in[5];
    const float* bv = (const float*)d_in[6];
    const float* Wo = (const float*)d_in[7];
    const float* bo = (const float*)d_in[8];
    float* out = (float*)d_out;

    float *q, *k, *v, *ctx;
    cudaGetSymbolAddress((void**)&q,   g_q);
    cudaGetSymbolAddress((void**)&k,   g_k);
    cudaGetSymbolAddress((void**)&v,   g_v);
    cudaGetSymbolAddress((void**)&ctx, g_ctx);

    cudaFuncSetAttribute(tf32_gemm_kernel,
                         cudaFuncAttributeMaxDynamicSharedMemorySize, GEMM_SMEM_TF);
    cudaFuncSetAttribute(attn3_kernel,
                         cudaFuncAttributeMaxDynamicSharedMemorySize, ATTN_SMEM);

    // Q, K: exact fp32 FFMA2 (floor-sensitive path)
    dim3 gqk(Dd / 128, (Mrows + 127) / 128, 2);   // 6 x 99 x 2
    qk_kernel<<<gqk, 256>>>(x, Wq, Wk, bq, bk, q, k);

    // V: tf32 3-product (smooth path)
    dim3 gtf(Dd / 128, (Mrows + 255) / 256);      // 6 x 50
    tf32_gemm_kernel<<<gtf, 256, GEMM_SMEM_TF>>>(x, Wv, bv, v, 0);

    attn3_kernel<<<Bc * Hh, 32 * NW, ATTN_SMEM>>>(q, k, v, ctx);

    // O: tf32 3-product
    tf32_gemm_kernel<<<gtf, 256, GEMM_SMEM_TF>>>(ctx, Wo, bo, out, 1);
}

// round 10
// speedup vs baseline: 1.1642x; 1.1642x over previous
#include <cuda_runtime.h>
#include <cuda_bf16.h>
#include <math.h>
#include <cstdint>

#define Bc 64
#define Tt 197
#define Dd 768
#define Hh 12
#define DKk 64
#define Mrows (Bc * Tt)   // 12608

typedef unsigned long long u64;

// ===== f32x2 helpers =====
__device__ __forceinline__ u64 pk2(float lo, float hi) {
    u64 r; asm("mov.b64 %0,{%1,%2};" : "=l"(r) : "f"(lo), "f"(hi)); return r;
}
__device__ __forceinline__ float2 upk2(u64 v) {
    float2 f; asm("mov.b64 {%0,%1},%2;" : "=f"(f.x), "=f"(f.y) : "l"(v)); return f;
}
__device__ __forceinline__ void ffma2(u64 &c, u64 a, u64 b) {
    asm("fma.rn.f32x2 %0,%1,%2,%0;" : "+l"(c) : "l"(a), "l"(b));
}

// ===== tf32 / mma.sync helpers =====
__device__ __forceinline__ uint32_t smem_u32(const void* p) {
    uint32_t a;
    asm("{ .reg .u64 t; cvta.to.shared.u64 t, %1; cvt.u32.u64 %0, t; }" : "=r"(a) : "l"(p));
    return a;
}
__device__ __forceinline__ float tf32r(float v) {
    uint32_t h;
    asm("cvt.rna.tf32.f32 %0, %1;" : "=r"(h) : "f"(v));
    return __uint_as_float(h);
}
__device__ __forceinline__ void ldsm4(uint32_t* r, uint32_t addr) {
    asm volatile("ldmatrix.sync.aligned.m8n8.x4.shared.b16 {%0,%1,%2,%3}, [%4];"
                 : "=r"(r[0]), "=r"(r[1]), "=r"(r[2]), "=r"(r[3]) : "r"(addr));
}
__device__ __forceinline__ void mma8(float* d, const uint32_t* a, uint32_t b0, uint32_t b1) {
    asm volatile(
        "mma.sync.aligned.m16n8k8.row.col.f32.tf32.tf32.f32 "
        "{%0,%1,%2,%3},{%4,%5,%6,%7},{%8,%9},{%0,%1,%2,%3};"
        : "+f"(d[0]), "+f"(d[1]), "+f"(d[2]), "+f"(d[3])
        : "r"(a[0]), "r"(a[1]), "r"(a[2]), "r"(a[3]), "r"(b0), "r"(b1));
}

// ===== scratch =====
__device__ float g_q[Bc * Hh * Tt * DKk];
__device__ float g_k[Bc * Hh * Tt * DKk];
__device__ float g_v[Bc * Hh * Tt * DKk];
__device__ float g_ctx[Bc * Tt * Dd];

// ---------------------------------------------------------------------------
// FFMA2 GEMM (exact fp32) for Q/K projections — proven R4 core.
// ---------------------------------------------------------------------------
#define KT 16

__device__ __forceinline__ void gemm_core(
    const float* __restrict__ A, const float* __restrict__ W,
    const float* __restrict__ bias, float* __restrict__ out,
    float* As, float* Ws)
{
    const int tid = threadIdx.x;
    const int tx = tid & 15;
    const int ty = tid >> 4;
    const int m0 = blockIdx.y * 128;
    const int n0 = blockIdx.x * 128;

    u64 c2[4][8];
#pragma unroll
    for (int i = 0; i < 4; i++)
#pragma unroll
        for (int j = 0; j < 8; j++) c2[i][j] = 0ull;

    const int ar = tid >> 1;
    const int ah = tid & 1;
    const int wk = tid >> 5;
    const int wc = tid & 31;

    float4 a0, a1, w0, w1;
    {
        a0 = make_float4(0.f, 0.f, 0.f, 0.f); a1 = a0;
        if (m0 + ar < Mrows) {
            const float* Ap = A + (size_t)(m0 + ar) * Dd + ah * 8;
            a0 = *(const float4*)Ap;
            a1 = *(const float4*)(Ap + 4);
        }
        const float* Wp = W + (size_t)wk * Dd + n0 + wc * 4;
        w0 = *(const float4*)Wp;
        w1 = *(const float4*)(Wp + 8 * Dd);
    }

    for (int k0 = 0; k0 < Dd; k0 += KT) {
        __syncthreads();
        As[(ah * 8 + 0) * 128 + ar] = a0.x; As[(ah * 8 + 1) * 128 + ar] = a0.y;
        As[(ah * 8 + 2) * 128 + ar] = a0.z; As[(ah * 8 + 3) * 128 + ar] = a0.w;
        As[(ah * 8 + 4) * 128 + ar] = a1.x; As[(ah * 8 + 5) * 128 + ar] = a1.y;
        As[(ah * 8 + 6) * 128 + ar] = a1.z; As[(ah * 8 + 7) * 128 + ar] = a1.w;
        *(float4*)&Ws[wk * 128 + wc * 4]       = w0;
        *(float4*)&Ws[(wk + 8) * 128 + wc * 4] = w1;
        __syncthreads();

        if (k0 + KT < Dd) {
            a0 = make_float4(0.f, 0.f, 0.f, 0.f); a1 = a0;
            if (m0 + ar < Mrows) {
                const float* Ap = A + (size_t)(m0 + ar) * Dd + (k0 + KT) + ah * 8;
                a0 = *(const float4*)Ap;
                a1 = *(const float4*)(Ap + 4);
            }
            const float* Wp = W + (size_t)(k0 + KT + wk) * Dd + n0 + wc * 4;
            w0 = *(const float4*)Wp;
            w1 = *(const float4*)(Wp + 8 * Dd);
        }

#pragma unroll
        for (int kk = 0; kk < KT; kk++) {
            const float* Ak = As + kk * 128;
            const float* Wr = Ws + kk * 128;
            u64 ap[4];
            ap[0] = *(const u64*)&Ak[ty * 4];
            ap[1] = *(const u64*)&Ak[ty * 4 + 2];
            ap[2] = *(const u64*)&Ak[64 + ty * 4];
            ap[3] = *(const u64*)&Ak[64 + ty * 4 + 2];
            float4 bv0 = *(const float4*)&Wr[tx * 4];
            float4 bv1 = *(const float4*)&Wr[64 + tx * 4];
            u64 bd[8];
            bd[0] = pk2(bv0.x, bv0.x); bd[1] = pk2(bv0.y, bv0.y);
            bd[2] = pk2(bv0.z, bv0.z); bd[3] = pk2(bv0.w, bv0.w);
            bd[4] = pk2(bv1.x, bv1.x); bd[5] = pk2(bv1.y, bv1.y);
            bd[6] = pk2(bv1.z, bv1.z); bd[7] = pk2(bv1.w, bv1.w);
#pragma unroll
            for (int i = 0; i < 4; i++)
#pragma unroll
                for (int j = 0; j < 8; j++) ffma2(c2[i][j], ap[i], bd[j]);
        }
    }

#pragma unroll
    for (int i = 0; i < 4; i++) {
        int rbase = m0 + ((i < 2) ? (ty * 4 + i * 2) : (64 + ty * 4 + (i - 2) * 2));
#pragma unroll
        for (int j = 0; j < 8; j++) {
            int cidx = n0 + ((j < 4) ? (tx * 4 + j) : (64 + tx * 4 + (j - 4)));
            float2 f = upk2(c2[i][j]);
            float bia = bias[cidx];
            f.x += bia; f.y += bia;
#pragma unroll
            for (int s = 0; s < 2; s++) {
                int r = rbase + s;
                if (r >= Mrows) continue;
                float v = s ? f.y : f.x;
                int bi = r / Tt, t = r - (r / Tt) * Tt;
                int h = cidx >> 6, dk = cidx & 63;
                out[(((size_t)(bi * Hh + h)) * Tt + t) * DKk + dk] = v;
            }
        }
    }
}

__global__ void __launch_bounds__(256, 2) qk_kernel(
    const float* __restrict__ x,
    const float* __restrict__ Wq, const float* __restrict__ Wk2,
    const float* __restrict__ bq, const float* __restrict__ bk2,
    float* __restrict__ q, float* __restrict__ k)
{
    __shared__ float As[KT * 128];
    __shared__ float Ws[KT * 128];
    int z = blockIdx.z;
    gemm_core(x, z ? Wk2 : Wq, z ? bk2 : bq, z ? k : q, As, Ws);
}

// ---------------------------------------------------------------------------
// 2-limb 3-product TF32 GEMM v2 (V, O): CTA 128x128, 128 threads, 4 warps,
// warp tile 64x64. Fragment sharing (Ah/Am/Bh/Bm once per k8 -> 3 products).
// W stores: thread t owns n-col t (float4 runs, 4-way max conflicts).
// ---------------------------------------------------------------------------
#define SA 36
#define GEMM_SMEM_TF ((128 + 128) * SA * 4)   // 36864

__global__ void __launch_bounds__(128, 2) tf32_gemm_kernel(
    const float* __restrict__ A, const float* __restrict__ W,
    const float* __restrict__ bias, float* __restrict__ out, int mode)
{
    extern __shared__ float smf[];
    float* As = smf;              // [128][SA]
    float* Ws = smf + 128 * SA;   // [128][SA]
    const uint32_t Asu = smem_u32(As);
    const uint32_t Wsu = smem_u32(Ws);

    const int tid  = threadIdx.x;
    const int lane = tid & 31;
    const int wid  = tid >> 5;
    const int wm   = wid >> 1;        // 0..1
    const int wn   = wid & 1;         // 0..1
    const int m0   = blockIdx.y * 128;
    const int n0   = blockIdx.x * 128;

    float d[4][8][4];
#pragma unroll
    for (int mf = 0; mf < 4; mf++)
#pragma unroll
        for (int nf = 0; nf < 8; nf++)
#pragma unroll
            for (int i = 0; i < 4; i++) d[mf][nf][i] = 0.f;

    const int a_row = wm * 64 + (lane & 15);
    const int a_co  = (lane >> 4) << 2;
    const int b_row = wn * 64 + ((lane >> 4) << 3) + (lane & 7);
    const int b_co  = ((lane >> 3) & 1) << 2;

    float4 pa[4];
    float  pw[16];

    {   // prefetch chunk 0: A row m0+tid, W column n0+tid
        const int r = m0 + tid;
        if (r < Mrows) {
            const float* Ap = A + (size_t)r * Dd;
#pragma unroll
            for (int i = 0; i < 4; i++) pa[i] = *(const float4*)(Ap + i * 4);
        } else {
#pragma unroll
            for (int i = 0; i < 4; i++) pa[i] = make_float4(0.f, 0.f, 0.f, 0.f);
        }
#pragma unroll
        for (int kq = 0; kq < 16; kq++)
            pw[kq] = W[(size_t)kq * Dd + n0 + tid];
    }

    for (int c = 0; c < Dd / 16; c++) {
        __syncthreads();
        // A limbs: row tid
#pragma unroll
        for (int i = 0; i < 4; i++) {
            float vv[4] = {pa[i].x, pa[i].y, pa[i].z, pa[i].w};
            float h[4], m[4];
#pragma unroll
            for (int j = 0; j < 4; j++) {
                h[j] = tf32r(vv[j]);
                m[j] = tf32r(vv[j] - h[j]);
            }
            *(float4*)&As[tid * SA + i * 4]      = make_float4(h[0], h[1], h[2], h[3]);
            *(float4*)&As[tid * SA + 16 + i * 4] = make_float4(m[0], m[1], m[2], m[3]);
        }
        // W limbs: n-column tid (transposed row of Ws)
        {
            float h[16], m[16];
#pragma unroll
            for (int kq = 0; kq < 16; kq++) {
                h[kq] = tf32r(pw[kq]);
                m[kq] = tf32r(pw[kq] - h[kq]);
            }
#pragma unroll
            for (int i = 0; i < 4; i++) {
                *(float4*)&Ws[tid * SA + i * 4]      = make_float4(h[i*4], h[i*4+1], h[i*4+2], h[i*4+3]);
                *(float4*)&Ws[tid * SA + 16 + i * 4] = make_float4(m[i*4], m[i*4+1], m[i*4+2], m[i*4+3]);
            }
        }
        __syncthreads();

        // prefetch next chunk
        if (c + 1 < Dd / 16) {
            const int r = m0 + tid;
            if (r < Mrows) {
                const float* Ap = A + (size_t)r * Dd + (c + 1) * 16;
#pragma unroll
                for (int i = 0; i < 4; i++) pa[i] = *(const float4*)(Ap + i * 4);
            } else {
#pragma unroll
                for (int i = 0; i < 4; i++) pa[i] = make_float4(0.f, 0.f, 0.f, 0.f);
            }
#pragma unroll
            for (int kq = 0; kq < 16; kq++)
                pw[kq] = W[(size_t)((c + 1) * 16 + kq) * Dd + n0 + tid];
        }

        // compute: per k8-step load Ah/Am/Bh/Bm once, run 3 products
#pragma unroll
        for (int kk = 0; kk < 16; kk += 8) {
            uint32_t ah[4][4], am[4][4], bh[4][4], bm[4][4];
#pragma unroll
            for (int mf = 0; mf < 4; mf++) {
                const uint32_t base = Asu + (uint32_t)(((a_row + mf * 16) * SA) + kk + a_co) * 4u;
                ldsm4(ah[mf], base);
                ldsm4(am[mf], base + 64u);   // +16 floats
            }
#pragma unroll
            for (int g = 0; g < 4; g++) {
                const uint32_t base = Wsu + (uint32_t)(((b_row + g * 16) * SA) + kk + b_co) * 4u;
                ldsm4(bh[g], base);
                ldsm4(bm[g], base + 64u);
            }
            // hh
#pragma unroll
            for (int mf = 0; mf < 4; mf++)
#pragma unroll
                for (int nf = 0; nf < 8; nf++)
                    mma8(d[mf][nf], ah[mf], bh[nf >> 1][(nf & 1) * 2], bh[nf >> 1][(nf & 1) * 2 + 1]);
            // hm
#pragma unroll
            for (int mf = 0; mf < 4; mf++)
#pragma unroll
                for (int nf = 0; nf < 8; nf++)
                    mma8(d[mf][nf], ah[mf], bm[nf >> 1][(nf & 1) * 2], bm[nf >> 1][(nf & 1) * 2 + 1]);
            // mh
#pragma unroll
            for (int mf = 0; mf < 4; mf++)
#pragma unroll
                for (int nf = 0; nf < 8; nf++)
                    mma8(d[mf][nf], am[mf], bh[nf >> 1][(nf & 1) * 2], bh[nf >> 1][(nf & 1) * 2 + 1]);
        }
    }

    // epilogue
    const int gid = lane >> 2, tig = lane & 3;
#pragma unroll
    for (int mf = 0; mf < 4; mf++) {
        const int r0 = m0 + wm * 64 + mf * 16 + gid;
        const int r1 = r0 + 8;
        int bi0 = 0, t0 = 0, bi1 = 0, t1 = 0;
        const bool v0 = (r0 < Mrows), v1 = (r1 < Mrows);
        if (v0) { bi0 = r0 / Tt; t0 = r0 - bi0 * Tt; }
        if (v1) { bi1 = r1 / Tt; t1 = r1 - bi1 * Tt; }
#pragma unroll
        for (int nf = 0; nf < 8; nf++) {
            const int cg = n0 + wn * 64 + nf * 8 + tig * 2;
            const float bx = bias[cg], by = bias[cg + 1];
            float2 o0 = make_float2(d[mf][nf][0] + bx, d[mf][nf][1] + by);
            float2 o1 = make_float2(d[mf][nf][2] + bx, d[mf][nf][3] + by);
            if (mode == 0) {
                const int h = cg >> 6, dk = cg & 63;
                if (v0) *(float2*)&out[(((size_t)(bi0 * Hh + h)) * Tt + t0) * DKk + dk] = o0;
                if (v1) *(float2*)&out[(((size_t)(bi1 * Hh + h)) * Tt + t1) * DKk + dk] = o1;
            } else {
                if (v0) *(float2*)&out[(size_t)r0 * Dd + cg] = o0;
                if (v1) *(float2*)&out[(size_t)r1 * Dd + cg] = o1;
            }
        }
    }
}

// ---------------------------------------------------------------------------
// Attention (unchanged): per (b,h) CTA, 16 warps, 4 rows/warp, rotated smem.
// ---------------------------------------------------------------------------
#define NW 16
#define ATTN_SMEM ((2 * Tt * 64 + NW * 800) * 4)

__global__ void __launch_bounds__(32 * NW) attn3_kernel(
    const float* __restrict__ Q, const float* __restrict__ K,
    const float* __restrict__ V, float* __restrict__ ctx)
{
    extern __shared__ float sm[];
    float* Ks = sm;
    float* Vs = sm + Tt * 64;
    const int tid  = threadIdx.x;
    const int lane = tid & 31;
    const int w    = tid >> 5;
    float* Pg = sm + 2 * Tt * 64 + w * 800;

    const int bh = blockIdx.x;
    const int b  = bh / Hh;
    const int h  = bh - b * Hh;

    const float* Kb = K + (size_t)bh * Tt * DKk;
    const float* Vb = V + (size_t)bh * Tt * DKk;
    const float* Qb = Q + (size_t)bh * Tt * DKk;

    for (int e = tid; e < Tt * 32; e += 32 * NW) {
        int j = e >> 5, p = e & 31, c = 2 * p;
        int off = j * 64 + ((c + 2 * j) & 63);
        *(float2*)&Ks[off] = *(const float2*)&Kb[j * 64 + c];
        *(float2*)&Vs[off] = *(const float2*)&Vb[j * 64 + c];
    }
    __syncthreads();

    int jj[7], rot[7];
#pragma unroll
    for (int u = 0; u < 7; u++) {
        int j = lane + 32 * u;
        jj[u]  = (j > Tt - 1) ? (Tt - 1) : j;
        rot[u] = (2 * jj[u]) & 63;
    }
    const int myc = 2 * lane;

    for (int g = w; g < 50; g += NW) {
        const int r0 = g * 4;
        int rs[4];
#pragma unroll
        for (int s = 0; s < 4; s++) rs[s] = (r0 + s > Tt - 1) ? (Tt - 1) : (r0 + s);

        u64 acc[4][7];
#pragma unroll
        for (int s = 0; s < 4; s++)
#pragma unroll
            for (int u = 0; u < 7; u++) acc[s][u] = 0ull;

#pragma unroll
        for (int dc = 0; dc < 8; dc++) {
            u64 qp[4][4];
#pragma unroll
            for (int s = 0; s < 4; s++) {
                const float* qs = Qb + rs[s] * DKk + dc * 8;
                float4 qa = *(const float4*)qs;
                float4 qb = *(const float4*)(qs + 4);
                qp[s][0] = pk2(qa.x, qa.y); qp[s][1] = pk2(qa.z, qa.w);
                qp[s][2] = pk2(qb.x, qb.y); qp[s][3] = pk2(qb.z, qb.w);
            }
            const int c0 = dc * 8;
#pragma unroll
            for (int u = 0; u < 7; u++) {
                const float* kr = Ks + jj[u] * 64;
                u64 kp0 = *(const u64*)&kr[(c0 + 0 + rot[u]) & 63];
                u64 kp1 = *(const u64*)&kr[(c0 + 2 + rot[u]) & 63];
                u64 kp2 = *(const u64*)&kr[(c0 + 4 + rot[u]) & 63];
                u64 kp3 = *(const u64*)&kr[(c0 + 6 + rot[u]) & 63];
#pragma unroll
                for (int s = 0; s < 4; s++) {
                    ffma2(acc[s][u], qp[s][0], kp0);
                    ffma2(acc[s][u], qp[s][1], kp1);
                    ffma2(acc[s][u], qp[s][2], kp2);
                    ffma2(acc[s][u], qp[s][3], kp3);
                }
            }
        }

        float iv[4];
#pragma unroll
        for (int s = 0; s < 4; s++) {
            float sc[7];
            float mx = -1e30f;
#pragma unroll
            for (int u = 0; u < 7; u++) {
                float2 f = upk2(acc[s][u]);
                float val = floorf((f.x + f.y) * 0.125f);
                sc[u] = (lane + 32 * u < Tt) ? val : -1e30f;
                mx = fmaxf(mx, sc[u]);
            }
#pragma unroll
            for (int o = 16; o; o >>= 1) mx = fmaxf(mx, __shfl_xor_sync(0xffffffffu, mx, o));
            float sum = 0.f;
#pragma unroll
            for (int u = 0; u < 7; u++) {
                if (lane + 32 * u < Tt) {
                    float p = __expf(sc[u] - mx);
                    Pg[jj[u] * 4 + s] = p;
                    sum += p;
                }
            }
#pragma unroll
            for (int o = 16; o; o >>= 1) sum += __shfl_xor_sync(0xffffffffu, sum, o);
            iv[s] = 1.f / sum;
        }
        __syncwarp();

        u64 a[4] = {0ull, 0ull, 0ull, 0ull};
        for (int j = 0; j < Tt - 1; j += 2) {
            u64 v0 = *(const u64*)&Vs[j * 64 + ((myc + 2 * j) & 63)];
            u64 v1 = *(const u64*)&Vs[(j + 1) * 64 + ((myc + 2 * j + 2) & 63)];
            float4 pa = *(const float4*)&Pg[j * 4];
            float4 pb = *(const float4*)&Pg[j * 4 + 4];
            ffma2(a[0], pk2(pa.x, pa.x), v0); ffma2(a[0], pk2(pb.x, pb.x), v1);
            ffma2(a[1], pk2(pa.y, pa.y), v0); ffma2(a[1], pk2(pb.y, pb.y), v1);
            ffma2(a[2], pk2(pa.z, pa.z), v0); ffma2(a[2], pk2(pb.z, pb.z), v1);
            ffma2(a[3], pk2(pa.w, pa.w), v0); ffma2(a[3], pk2(pb.w, pb.w), v1);
        }
        {
            int j = Tt - 1;
            u64 v0 = *(const u64*)&Vs[j * 64 + ((myc + 2 * j) & 63)];
            float4 pa = *(const float4*)&Pg[j * 4];
            ffma2(a[0], pk2(pa.x, pa.x), v0);
            ffma2(a[1], pk2(pa.y, pa.y), v0);
            ffma2(a[2], pk2(pa.z, pa.z), v0);
            ffma2(a[3], pk2(pa.w, pa.w), v0);
        }

#pragma unroll
        for (int s = 0; s < 4; s++) {
            float2 o = upk2(a[s]);
            o.x *= iv[s]; o.y *= iv[s];
            *(float2*)&ctx[((size_t)(b * Tt + rs[s])) * Dd + h * DKk + myc] = o;
        }
        __syncwarp();
    }
}

// ---------------------------------------------------------------------------
extern "C" void kernel_launch(void* const* d_in, const int* in_sizes, int n_in,
                              void* d_out, int out_size)
{
    const float* x  = (const float*)d_in[0];
    const float* Wq = (const float*)d_in[1];
    const float* bq = (const float*)d_in[2];
    const float* Wk = (const float*)d_in[3];
    const float* bk = (const float*)d_in[4];
    const float* Wv = (const float*)d_in[5];
    const float* bv = (const float*)d_in[6];
    const float* Wo = (const float*)d_in[7];
    const float* bo = (const float*)d_in[8];
    float* out = (float*)d_out;

    float *q, *k, *v, *ctx;
    cudaGetSymbolAddress((void**)&q,   g_q);
    cudaGetSymbolAddress((void**)&k,   g_k);
    cudaGetSymbolAddress((void**)&v,   g_v);
    cudaGetSymbolAddress((void**)&ctx, g_ctx);

    cudaFuncSetAttribute(tf32_gemm_kernel,
                         cudaFuncAttributeMaxDynamicSharedMemorySize, GEMM_SMEM_TF);
    cudaFuncSetAttribute(attn3_kernel,
                         cudaFuncAttributeMaxDynamicSharedMemorySize, ATTN_SMEM);

    // Q, K: exact fp32 FFMA2 (floor-sensitive path)
    dim3 gqk(Dd / 128, (Mrows + 127) / 128, 2);   // 6 x 99 x 2
    qk_kernel<<<gqk, 256>>>(x, Wq, Wk, bq, bk, q, k);

    // V: tf32 3-product v2 (smooth path)
    dim3 gtf(Dd / 128, (Mrows + 127) / 128);      // 6 x 99
    tf32_gemm_kernel<<<gtf, 128, GEMM_SMEM_TF>>>(x, Wv, bv, v, 0);

    attn3_kernel<<<Bc * Hh, 32 * NW, ATTN_SMEM>>>(q, k, v, ctx);

    // O: tf32 3-product v2
    tf32_gemm_kernel<<<gtf, 128, GEMM_SMEM_TF>>>(ctx, Wo, bo, out, 1);
}

// round 12
// speedup vs baseline: 1.3694x; 1.1763x over previous
#include <cuda_runtime.h>
#include <cuda_bf16.h>
#include <math.h>
#include <cstdint>

#define Bc 64
#define Tt 197
#define Dd 768
#define Hh 12
#define DKk 64
#define Mrows (Bc * Tt)   // 12608

typedef unsigned long long u64;

// ===== f32x2 helpers =====
__device__ __forceinline__ u64 pk2(float lo, float hi) {
    u64 r; asm("mov.b64 %0,{%1,%2};" : "=l"(r) : "f"(lo), "f"(hi)); return r;
}
__device__ __forceinline__ float2 upk2(u64 v) {
    float2 f; asm("mov.b64 {%0,%1},%2;" : "=f"(f.x), "=f"(f.y) : "l"(v)); return f;
}
__device__ __forceinline__ void ffma2(u64 &c, u64 a, u64 b) {
    asm("fma.rn.f32x2 %0,%1,%2,%0;" : "+l"(c) : "l"(a), "l"(b));
}

// ===== mma helpers =====
__device__ __forceinline__ uint32_t smem_u32(const void* p) {
    uint32_t a;
    asm("{ .reg .u64 t; cvta.to.shared.u64 t, %1; cvt.u32.u64 %0, t; }" : "=r"(a) : "l"(p));
    return a;
}
__device__ __forceinline__ void ldsm4(uint32_t* r, uint32_t addr) {
    asm volatile("ldmatrix.sync.aligned.m8n8.x4.shared.b16 {%0,%1,%2,%3}, [%4];"
                 : "=r"(r[0]), "=r"(r[1]), "=r"(r[2]), "=r"(r[3]) : "r"(addr));
}
__device__ __forceinline__ void mma16(float* d, const uint32_t* a, uint32_t b0, uint32_t b1) {
    asm volatile(
        "mma.sync.aligned.m16n8k16.row.col.f32.bf16.bf16.f32 "
        "{%0,%1,%2,%3},{%4,%5,%6,%7},{%8,%9},{%0,%1,%2,%3};"
        : "+f"(d[0]), "+f"(d[1]), "+f"(d[2]), "+f"(d[3])
        : "r"(a[0]), "r"(a[1]), "r"(a[2]), "r"(a[3]), "r"(b0), "r"(b1));
}

// ===== scratch =====
__device__ float g_q[Bc * Hh * Tt * DKk];
__device__ float g_k[Bc * Hh * Tt * DKk];
__device__ float g_v[Bc * Hh * Tt * DKk];
__device__ float g_ctx[Bc * Tt * Dd];

// ---------------------------------------------------------------------------
// FFMA2 GEMM (exact fp32) for Q/K projections — proven R4 core.
// ---------------------------------------------------------------------------
#define KT 16

__device__ __forceinline__ void gemm_core(
    const float* __restrict__ A, const float* __restrict__ W,
    const float* __restrict__ bias, float* __restrict__ out,
    float* As, float* Ws)
{
    const int tid = threadIdx.x;
    const int tx = tid & 15;
    const int ty = tid >> 4;
    const int m0 = blockIdx.y * 128;
    const int n0 = blockIdx.x * 128;

    u64 c2[4][8];
#pragma unroll
    for (int i = 0; i < 4; i++)
#pragma unroll
        for (int j = 0; j < 8; j++) c2[i][j] = 0ull;

    const int ar = tid >> 1;
    const int ah = tid & 1;
    const int wk = tid >> 5;
    const int wc = tid & 31;

    float4 a0, a1, w0, w1;
    {
        a0 = make_float4(0.f, 0.f, 0.f, 0.f); a1 = a0;
        if (m0 + ar < Mrows) {
            const float* Ap = A + (size_t)(m0 + ar) * Dd + ah * 8;
            a0 = *(const float4*)Ap;
            a1 = *(const float4*)(Ap + 4);
        }
        const float* Wp = W + (size_t)wk * Dd + n0 + wc * 4;
        w0 = *(const float4*)Wp;
        w1 = *(const float4*)(Wp + 8 * Dd);
    }

    for (int k0 = 0; k0 < Dd; k0 += KT) {
        __syncthreads();
        As[(ah * 8 + 0) * 128 + ar] = a0.x; As[(ah * 8 + 1) * 128 + ar] = a0.y;
        As[(ah * 8 + 2) * 128 + ar] = a0.z; As[(ah * 8 + 3) * 128 + ar] = a0.w;
        As[(ah * 8 + 4) * 128 + ar] = a1.x; As[(ah * 8 + 5) * 128 + ar] = a1.y;
        As[(ah * 8 + 6) * 128 + ar] = a1.z; As[(ah * 8 + 7) * 128 + ar] = a1.w;
        *(float4*)&Ws[wk * 128 + wc * 4]       = w0;
        *(float4*)&Ws[(wk + 8) * 128 + wc * 4] = w1;
        __syncthreads();

        if (k0 + KT < Dd) {
            a0 = make_float4(0.f, 0.f, 0.f, 0.f); a1 = a0;
            if (m0 + ar < Mrows) {
                const float* Ap = A + (size_t)(m0 + ar) * Dd + (k0 + KT) + ah * 8;
                a0 = *(const float4*)Ap;
                a1 = *(const float4*)(Ap + 4);
            }
            const float* Wp = W + (size_t)(k0 + KT + wk) * Dd + n0 + wc * 4;
            w0 = *(const float4*)Wp;
            w1 = *(const float4*)(Wp + 8 * Dd);
        }

#pragma unroll
        for (int kk = 0; kk < KT; kk++) {
            const float* Ak = As + kk * 128;
            const float* Wr = Ws + kk * 128;
            u64 ap[4];
            ap[0] = *(const u64*)&Ak[ty * 4];
            ap[1] = *(const u64*)&Ak[ty * 4 + 2];
            ap[2] = *(const u64*)&Ak[64 + ty * 4];
            ap[3] = *(const u64*)&Ak[64 + ty * 4 + 2];
            float4 bv0 = *(const float4*)&Wr[tx * 4];
            float4 bv1 = *(const float4*)&Wr[64 + tx * 4];
            u64 bd[8];
            bd[0] = pk2(bv0.x, bv0.x); bd[1] = pk2(bv0.y, bv0.y);
            bd[2] = pk2(bv0.z, bv0.z); bd[3] = pk2(bv0.w, bv0.w);
            bd[4] = pk2(bv1.x, bv1.x); bd[5] = pk2(bv1.y, bv1.y);
            bd[6] = pk2(bv1.z, bv1.z); bd[7] = pk2(bv1.w, bv1.w);
#pragma unroll
            for (int i = 0; i < 4; i++)
#pragma unroll
                for (int j = 0; j < 8; j++) ffma2(c2[i][j], ap[i], bd[j]);
        }
    }

#pragma unroll
    for (int i = 0; i < 4; i++) {
        int rbase = m0 + ((i < 2) ? (ty * 4 + i * 2) : (64 + ty * 4 + (i - 2) * 2));
#pragma unroll
        for (int j = 0; j < 8; j++) {
            int cidx = n0 + ((j < 4) ? (tx * 4 + j) : (64 + tx * 4 + (j - 4)));
            float2 f = upk2(c2[i][j]);
            float bia = bias[cidx];
            f.x += bia; f.y += bia;
#pragma unroll
            for (int s = 0; s < 2; s++) {
                int r = rbase + s;
                if (r >= Mrows) continue;
                float v = s ? f.y : f.x;
                int bi = r / Tt, t = r - (r / Tt) * Tt;
                int h = cidx >> 6, dk = cidx & 63;
                out[(((size_t)(bi * Hh + h)) * Tt + t) * DKk + dk] = v;
            }
        }
    }
}

__global__ void __launch_bounds__(256, 2) qk_kernel(
    const float* __restrict__ x,
    const float* __restrict__ Wq, const float* __restrict__ Wk2,
    const float* __restrict__ bq, const float* __restrict__ bk2,
    float* __restrict__ q, float* __restrict__ k)
{
    __shared__ float As[KT * 128];
    __shared__ float Ws[KT * 128];
    int z = blockIdx.z;
    gemm_core(x, z ? Wk2 : Wq, z ? bk2 : bq, z ? k : q, As, Ws);
}

// ---------------------------------------------------------------------------
// 2-limb 3-product BF16 GEMM (V, O): CTA 128x128, 128 threads, 4 warps,
// warp tile 64x64, m16n8k16. Limb planes in smem rows: [h 16 | m 16 | pad 8]
// bf16, row stride 40 b16 = 80 B (conflict-free ldsm + STS.128).
// Products: hh + hm + mh (residual ~2^-16 — smooth paths only).
// ---------------------------------------------------------------------------
#define RB 40                                  // row stride in bf16 units
#define GEMM_SMEM_BF ((128 + 128) * RB * 2)    // 20480 bytes

union Pack8 { __nv_bfloat16 b[8]; uint4 u; };

__global__ void __launch_bounds__(128, 2) bf16_gemm_kernel(
    const float* __restrict__ A, const float* __restrict__ W,
    const float* __restrict__ bias, float* __restrict__ out, int mode)
{
    extern __shared__ __nv_bfloat16 smb[];
    __nv_bfloat16* As = smb;              // [128][RB]
    __nv_bfloat16* Ws = smb + 128 * RB;   // [128][RB]
    const uint32_t Asu = smem_u32(As);
    const uint32_t Wsu = smem_u32(Ws);

    const int tid  = threadIdx.x;
    const int lane = tid & 31;
    const int wid  = tid >> 5;
    const int wm   = wid >> 1;        // 0..1
    const int wn   = wid & 1;         // 0..1
    const int m0   = blockIdx.y * 128;
    const int n0   = blockIdx.x * 128;

    float d[4][8][4];
#pragma unroll
    for (int mf = 0; mf < 4; mf++)
#pragma unroll
        for (int nf = 0; nf < 8; nf++)
#pragma unroll
            for (int i = 0; i < 4; i++) d[mf][nf][i] = 0.f;

    // ldsm byte-address bases
    const uint32_t a_base = Asu + (uint32_t)(wm * 64 + (lane & 15)) * 80u + ((lane >> 4) << 4);
    const uint32_t b_base = Wsu + (uint32_t)(wn * 64 + ((lane >> 4) << 3) + (lane & 7)) * 80u
                          + (((lane >> 3) & 1) << 4);

    float4 pa[4];
    float  pw[16];

    {   // prefetch chunk 0: A row m0+tid, W column n0+tid
        const int r = m0 + tid;
        if (r < Mrows) {
            const float* Ap = A + (size_t)r * Dd;
#pragma unroll
            for (int i = 0; i < 4; i++) pa[i] = *(const float4*)(Ap + i * 4);
        } else {
#pragma unroll
            for (int i = 0; i < 4; i++) pa[i] = make_float4(0.f, 0.f, 0.f, 0.f);
        }
#pragma unroll
        for (int kq = 0; kq < 16; kq++)
            pw[kq] = W[(size_t)kq * Dd + n0 + tid];
    }

    for (int c = 0; c < Dd / 16; c++) {
        __syncthreads();
        // A limbs: row tid
        {
            float vv[16];
#pragma unroll
            for (int i = 0; i < 4; i++) {
                vv[i * 4 + 0] = pa[i].x; vv[i * 4 + 1] = pa[i].y;
                vv[i * 4 + 2] = pa[i].z; vv[i * 4 + 3] = pa[i].w;
            }
            Pack8 h0, h1, m0p, m1p;
#pragma unroll
            for (int j = 0; j < 16; j++) {
                __nv_bfloat16 hb = __float2bfloat16_rn(vv[j]);
                __nv_bfloat16 mb = __float2bfloat16_rn(vv[j] - __bfloat162float(hb));
                if (j < 8) { h0.b[j] = hb; m0p.b[j] = mb; }
                else       { h1.b[j - 8] = hb; m1p.b[j - 8] = mb; }
            }
            __nv_bfloat16* Arow = As + tid * RB;
            *(uint4*)(Arow)      = h0.u;  *(uint4*)(Arow + 8)  = h1.u;
            *(uint4*)(Arow + 16) = m0p.u; *(uint4*)(Arow + 24) = m1p.u;
        }
        // W limbs: n-column tid
        {
            Pack8 h0, h1, m0p, m1p;
#pragma unroll
            for (int j = 0; j < 16; j++) {
                __nv_bfloat16 hb = __float2bfloat16_rn(pw[j]);
                __nv_bfloat16 mb = __float2bfloat16_rn(pw[j] - __bfloat162float(hb));
                if (j < 8) { h0.b[j] = hb; m0p.b[j] = mb; }
                else       { h1.b[j - 8] = hb; m1p.b[j - 8] = mb; }
            }
            __nv_bfloat16* Wrow = Ws + tid * RB;
            *(uint4*)(Wrow)      = h0.u;  *(uint4*)(Wrow + 8)  = h1.u;
            *(uint4*)(Wrow + 16) = m0p.u; *(uint4*)(Wrow + 24) = m1p.u;
        }
        __syncthreads();

        // prefetch next chunk
        if (c + 1 < Dd / 16) {
            const int r = m0 + tid;
            if (r < Mrows) {
                const float* Ap = A + (size_t)r * Dd + (c + 1) * 16;
#pragma unroll
                for (int i = 0; i < 4; i++) pa[i] = *(const float4*)(Ap + i * 4);
            } else {
#pragma unroll
                for (int i = 0; i < 4; i++) pa[i] = make_float4(0.f, 0.f, 0.f, 0.f);
            }
#pragma unroll
            for (int kq = 0; kq < 16; kq++)
                pw[kq] = W[(size_t)((c + 1) * 16 + kq) * Dd + n0 + tid];
        }

        // compute: one k16 step per chunk, 3 products
        uint32_t ah[4][4], am[4][4], bh[4][4], bm[4][4];
#pragma unroll
        for (int mf = 0; mf < 4; mf++) ldsm4(ah[mf], a_base + mf * 1280u);
#pragma unroll
        for (int g = 0; g < 4; g++)    ldsm4(bh[g], b_base + g * 1280u);
        // hh
#pragma unroll
        for (int mf = 0; mf < 4; mf++)
#pragma unroll
            for (int nf = 0; nf < 8; nf++)
                mma16(d[mf][nf], ah[mf], bh[nf >> 1][(nf & 1) * 2], bh[nf >> 1][(nf & 1) * 2 + 1]);
#pragma unroll
        for (int g = 0; g < 4; g++)    ldsm4(bm[g], b_base + g * 1280u + 32u);
        // hm
#pragma unroll
        for (int mf = 0; mf < 4; mf++)
#pragma unroll
            for (int nf = 0; nf < 8; nf++)
                mma16(d[mf][nf], ah[mf], bm[nf >> 1][(nf & 1) * 2], bm[nf >> 1][(nf & 1) * 2 + 1]);
#pragma unroll
        for (int mf = 0; mf < 4; mf++) ldsm4(am[mf], a_base + mf * 1280u + 32u);
        // mh
#pragma unroll
        for (int mf = 0; mf < 4; mf++)
#pragma unroll
            for (int nf = 0; nf < 8; nf++)
                mma16(d[mf][nf], am[mf], bh[nf >> 1][(nf & 1) * 2], bh[nf >> 1][(nf & 1) * 2 + 1]);
    }

    // epilogue (m16n8 D layout — same as tf32 path)
    const int gid = lane >> 2, tig = lane & 3;
#pragma unroll
    for (int mf = 0; mf < 4; mf++) {
        const int r0 = m0 + wm * 64 + mf * 16 + gid;
        const int r1 = r0 + 8;
        int bi0 = 0, t0 = 0, bi1 = 0, t1 = 0;
        const bool v0 = (r0 < Mrows), v1 = (r1 < Mrows);
        if (v0) { bi0 = r0 / Tt; t0 = r0 - bi0 * Tt; }
        if (v1) { bi1 = r1 / Tt; t1 = r1 - bi1 * Tt; }
#pragma unroll
        for (int nf = 0; nf < 8; nf++) {
            const int cg = n0 + wn * 64 + nf * 8 + tig * 2;
            const float bx = bias[cg], by = bias[cg + 1];
            float2 o0 = make_float2(d[mf][nf][0] + bx, d[mf][nf][1] + by);
            float2 o1 = make_float2(d[mf][nf][2] + bx, d[mf][nf][3] + by);
            if (mode == 0) {
                const int h = cg >> 6, dk = cg & 63;
                if (v0) *(float2*)&out[(((size_t)(bi0 * Hh + h)) * Tt + t0) * DKk + dk] = o0;
                if (v1) *(float2*)&out[(((size_t)(bi1 * Hh + h)) * Tt + t1) * DKk + dk] = o1;
            } else {
                if (v0) *(float2*)&out[(size_t)r0 * Dd + cg] = o0;
                if (v1) *(float2*)&out[(size_t)r1 * Dd + cg] = o1;
            }
        }
    }
}

// ---------------------------------------------------------------------------
// Attention (unchanged): per (b,h) CTA, 16 warps, 4 rows/warp, rotated smem.
// ---------------------------------------------------------------------------
#define NW 16
#define ATTN_SMEM ((2 * Tt * 64 + NW * 800) * 4)

__global__ void __launch_bounds__(32 * NW) attn3_kernel(
    const float* __restrict__ Q, const float* __restrict__ K,
    const float* __restrict__ V, float* __restrict__ ctx)
{
    extern __shared__ float sm[];
    float* Ks = sm;
    float* Vs = sm + Tt * 64;
    const int tid  = threadIdx.x;
    const int lane = tid & 31;
    const int w    = tid >> 5;
    float* Pg = sm + 2 * Tt * 64 + w * 800;

    const int bh = blockIdx.x;
    const int b  = bh / Hh;
    const int h  = bh - b * Hh;

    const float* Kb = K + (size_t)bh * Tt * DKk;
    const float* Vb = V + (size_t)bh * Tt * DKk;
    const float* Qb = Q + (size_t)bh * Tt * DKk;

    for (int e = tid; e < Tt * 32; e += 32 * NW) {
        int j = e >> 5, p = e & 31, c = 2 * p;
        int off = j * 64 + ((c + 2 * j) & 63);
        *(float2*)&Ks[off] = *(const float2*)&Kb[j * 64 + c];
        *(float2*)&Vs[off] = *(const float2*)&Vb[j * 64 + c];
    }
    __syncthreads();

    int jj[7], rot[7];
#pragma unroll
    for (int u = 0; u < 7; u++) {
        int j = lane + 32 * u;
        jj[u]  = (j > Tt - 1) ? (Tt - 1) : j;
        rot[u] = (2 * jj[u]) & 63;
    }
    const int myc = 2 * lane;

    for (int g = w; g < 50; g += NW) {
        const int r0 = g * 4;
        int rs[4];
#pragma unroll
        for (int s = 0; s < 4; s++) rs[s] = (r0 + s > Tt - 1) ? (Tt - 1) : (r0 + s);

        u64 acc[4][7];
#pragma unroll
        for (int s = 0; s < 4; s++)
#pragma unroll
            for (int u = 0; u < 7; u++) acc[s][u] = 0ull;

#pragma unroll
        for (int dc = 0; dc < 8; dc++) {
            u64 qp[4][4];
#pragma unroll
            for (int s = 0; s < 4; s++) {
                const float* qs = Qb + rs[s] * DKk + dc * 8;
                float4 qa = *(const float4*)qs;
                float4 qb = *(const float4*)(qs + 4);
                qp[s][0] = pk2(qa.x, qa.y); qp[s][1] = pk2(qa.z, qa.w);
                qp[s][2] = pk2(qb.x, qb.y); qp[s][3] = pk2(qb.z, qb.w);
            }
            const int c0 = dc * 8;
#pragma unroll
            for (int u = 0; u < 7; u++) {
                const float* kr = Ks + jj[u] * 64;
                u64 kp0 = *(const u64*)&kr[(c0 + 0 + rot[u]) & 63];
                u64 kp1 = *(const u64*)&kr[(c0 + 2 + rot[u]) & 63];
                u64 kp2 = *(const u64*)&kr[(c0 + 4 + rot[u]) & 63];
                u64 kp3 = *(const u64*)&kr[(c0 + 6 + rot[u]) & 63];
#pragma unroll
                for (int s = 0; s < 4; s++) {
                    ffma2(acc[s][u], qp[s][0], kp0);
                    ffma2(acc[s][u], qp[s][1], kp1);
                    ffma2(acc[s][u], qp[s][2], kp2);
                    ffma2(acc[s][u], qp[s][3], kp3);
                }
            }
        }

        float iv[4];
#pragma unroll
        for (int s = 0; s < 4; s++) {
            float sc[7];
            float mx = -1e30f;
#pragma unroll
            for (int u = 0; u < 7; u++) {
                float2 f = upk2(acc[s][u]);
                float val = floorf((f.x + f.y) * 0.125f);
                sc[u] = (lane + 32 * u < Tt) ? val : -1e30f;
                mx = fmaxf(mx, sc[u]);
            }
#pragma unroll
            for (int o = 16; o; o >>= 1) mx = fmaxf(mx, __shfl_xor_sync(0xffffffffu, mx, o));
            float sum = 0.f;
#pragma unroll
            for (int u = 0; u < 7; u++) {
                if (lane + 32 * u < Tt) {
                    float p = __expf(sc[u] - mx);
                    Pg[jj[u] * 4 + s] = p;
                    sum += p;
                }
            }
#pragma unroll
            for (int o = 16; o; o >>= 1) sum += __shfl_xor_sync(0xffffffffu, sum, o);
            iv[s] = 1.f / sum;
        }
        __syncwarp();

        u64 a[4] = {0ull, 0ull, 0ull, 0ull};
        for (int j = 0; j < Tt - 1; j += 2) {
            u64 v0 = *(const u64*)&Vs[j * 64 + ((myc + 2 * j) & 63)];
            u64 v1 = *(const u64*)&Vs[(j + 1) * 64 + ((myc + 2 * j + 2) & 63)];
            float4 pa = *(const float4*)&Pg[j * 4];
            float4 pb = *(const float4*)&Pg[j * 4 + 4];
            ffma2(a[0], pk2(pa.x, pa.x), v0); ffma2(a[0], pk2(pb.x, pb.x), v1);
            ffma2(a[1], pk2(pa.y, pa.y), v0); ffma2(a[1], pk2(pb.y, pb.y), v1);
            ffma2(a[2], pk2(pa.z, pa.z), v0); ffma2(a[2], pk2(pb.z, pb.z), v1);
            ffma2(a[3], pk2(pa.w, pa.w), v0); ffma2(a[3], pk2(pb.w, pb.w), v1);
        }
        {
            int j = Tt - 1;
            u64 v0 = *(const u64*)&Vs[j * 64 + ((myc + 2 * j) & 63)];
            float4 pa = *(const float4*)&Pg[j * 4];
            ffma2(a[0], pk2(pa.x, pa.x), v0);
            ffma2(a[1], pk2(pa.y, pa.y), v0);
            ffma2(a[2], pk2(pa.z, pa.z), v0);
            ffma2(a[3], pk2(pa.w, pa.w), v0);
        }

#pragma unroll
        for (int s = 0; s < 4; s++) {
            float2 o = upk2(a[s]);
            o.x *= iv[s]; o.y *= iv[s];
            *(float2*)&ctx[((size_t)(b * Tt + rs[s])) * Dd + h * DKk + myc] = o;
        }
        __syncwarp();
    }
}

// ---------------------------------------------------------------------------
extern "C" void kernel_launch(void* const* d_in, const int* in_sizes, int n_in,
                              void* d_out, int out_size)
{
    const float* x  = (const float*)d_in[0];
    const float* Wq = (const float*)d_in[1];
    const float* bq = (const float*)d_in[2];
    const float* Wk = (const float*)d_in[3];
    const float* bk = (const float*)d_in[4];
    const float* Wv = (const float*)d_in[5];
    const float* bv = (const float*)d_in[6];
    const float* Wo = (const float*)d_in[7];
    const float* bo = (const float*)d_in[8];
    float* out = (float*)d_out;

    float *q, *k, *v, *ctx;
    cudaGetSymbolAddress((void**)&q,   g_q);
    cudaGetSymbolAddress((void**)&k,   g_k);
    cudaGetSymbolAddress((void**)&v,   g_v);
    cudaGetSymbolAddress((void**)&ctx, g_ctx);

    cudaFuncSetAttribute(bf16_gemm_kernel,
                         cudaFuncAttributeMaxDynamicSharedMemorySize, GEMM_SMEM_BF);
    cudaFuncSetAttribute(attn3_kernel,
                         cudaFuncAttributeMaxDynamicSharedMemorySize, ATTN_SMEM);

    // Q, K: exact fp32 FFMA2 (floor-sensitive path)
    dim3 gqk(Dd / 128, (Mrows + 127) / 128, 2);   // 6 x 99 x 2
    qk_kernel<<<gqk, 256>>>(x, Wq, Wk, bq, bk, q, k);

    // V: bf16 2-limb 3-product (smooth path)
    dim3 gbf(Dd / 128, (Mrows + 127) / 128);      // 6 x 99
    bf16_gemm_kernel<<<gbf, 128, GEMM_SMEM_BF>>>(x, Wv, bv, v, 0);

    attn3_kernel<<<Bc * Hh, 32 * NW, ATTN_SMEM>>>(q, k, v, ctx);

    // O: bf16 2-limb 3-product
    bf16_gemm_kernel<<<gbf, 128, GEMM_SMEM_BF>>>(ctx, Wo, bo, out, 1);
}

// round 14
// speedup vs baseline: 1.3868x; 1.0127x over previous
#include <cuda_runtime.h>
#include <cuda_bf16.h>
#include <math.h>
#include <cstdint>

#define Bc 64
#define Tt 197
#define Dd 768
#define Hh 12
#define DKk 64
#define Mrows (Bc * Tt)   // 12608
#define NCH (Dd / 16)     // 48 K-chunks

typedef unsigned long long u64;

// ===== f32x2 helpers =====
__device__ __forceinline__ u64 pk2(float lo, float hi) {
    u64 r; asm("mov.b64 %0,{%1,%2};" : "=l"(r) : "f"(lo), "f"(hi)); return r;
}
__device__ __forceinline__ float2 upk2(u64 v) {
    float2 f; asm("mov.b64 {%0,%1},%2;" : "=f"(f.x), "=f"(f.y) : "l"(v)); return f;
}
__device__ __forceinline__ void ffma2(u64 &c, u64 a, u64 b) {
    asm("fma.rn.f32x2 %0,%1,%2,%0;" : "+l"(c) : "l"(a), "l"(b));
}

// ===== mma helpers =====
__device__ __forceinline__ uint32_t smem_u32(const void* p) {
    uint32_t a;
    asm("{ .reg .u64 t; cvta.to.shared.u64 t, %1; cvt.u32.u64 %0, t; }" : "=r"(a) : "l"(p));
    return a;
}
__device__ __forceinline__ void ldsm4(uint32_t* r, uint32_t addr) {
    asm volatile("ldmatrix.sync.aligned.m8n8.x4.shared.b16 {%0,%1,%2,%3}, [%4];"
                 : "=r"(r[0]), "=r"(r[1]), "=r"(r[2]), "=r"(r[3]) : "r"(addr));
}
__device__ __forceinline__ void mma16(float* d, const uint32_t* a, uint32_t b0, uint32_t b1) {
    asm volatile(
        "mma.sync.aligned.m16n8k16.row.col.f32.bf16.bf16.f32 "
        "{%0,%1,%2,%3},{%4,%5,%6,%7},{%8,%9},{%0,%1,%2,%3};"
        : "+f"(d[0]), "+f"(d[1]), "+f"(d[2]), "+f"(d[3])
        : "r"(a[0]), "r"(a[1]), "r"(a[2]), "r"(a[3]), "r"(b0), "r"(b1));
}

// ===== scratch =====
__device__ float g_q[Bc * Hh * Tt * DKk];
__device__ float g_k[Bc * Hh * Tt * DKk];
__device__ float g_v[Bc * Hh * Tt * DKk];
__device__ float g_ctx[Bc * Tt * Dd];

// ---------------------------------------------------------------------------
// FFMA2 GEMM (exact fp32) for Q/K — double-buffered smem ping-pong.
// 128x128 tile, KT=16, one __syncthreads per chunk.
// ---------------------------------------------------------------------------
#define KT 16

__device__ __forceinline__ void gemm_core(
    const float* __restrict__ A, const float* __restrict__ W,
    const float* __restrict__ bias, float* __restrict__ out,
    float* As /*[2][KT*128]*/, float* Ws /*[2][KT*128]*/)
{
    const int tid = threadIdx.x;
    const int tx = tid & 15;
    const int ty = tid >> 4;
    const int m0 = blockIdx.y * 128;
    const int n0 = blockIdx.x * 128;

    u64 c2[4][8];
#pragma unroll
    for (int i = 0; i < 4; i++)
#pragma unroll
        for (int j = 0; j < 8; j++) c2[i][j] = 0ull;

    const int ar = tid >> 1;
    const int ah = tid & 1;
    const int wk = tid >> 5;
    const int wc = tid & 31;
    const bool arow_ok = (m0 + ar < Mrows);

    float4 a0, a1, w0, w1;

    // chunk 0: LDG + store into buf0
    {
        a0 = make_float4(0.f, 0.f, 0.f, 0.f); a1 = a0;
        if (arow_ok) {
            const float* Ap = A + (size_t)(m0 + ar) * Dd + ah * 8;
            a0 = *(const float4*)Ap;
            a1 = *(const float4*)(Ap + 4);
        }
        const float* Wp = W + (size_t)wk * Dd + n0 + wc * 4;
        w0 = *(const float4*)Wp;
        w1 = *(const float4*)(Wp + 8 * Dd);

        float* Asb = As;
        float* Wsb = Ws;
        Asb[(ah * 8 + 0) * 128 + ar] = a0.x; Asb[(ah * 8 + 1) * 128 + ar] = a0.y;
        Asb[(ah * 8 + 2) * 128 + ar] = a0.z; Asb[(ah * 8 + 3) * 128 + ar] = a0.w;
        Asb[(ah * 8 + 4) * 128 + ar] = a1.x; Asb[(ah * 8 + 5) * 128 + ar] = a1.y;
        Asb[(ah * 8 + 6) * 128 + ar] = a1.z; Asb[(ah * 8 + 7) * 128 + ar] = a1.w;
        *(float4*)&Wsb[wk * 128 + wc * 4]       = w0;
        *(float4*)&Wsb[(wk + 8) * 128 + wc * 4] = w1;
    }
    __syncthreads();

    for (int c = 0; c < NCH; c++) {
        const int cur = c & 1;
        const bool has_next = (c + 1 < NCH);

        if (has_next) {   // LDG chunk c+1
            a0 = make_float4(0.f, 0.f, 0.f, 0.f); a1 = a0;
            if (arow_ok) {
                const float* Ap = A + (size_t)(m0 + ar) * Dd + (c + 1) * KT + ah * 8;
                a0 = *(const float4*)Ap;
                a1 = *(const float4*)(Ap + 4);
            }
            const float* Wp = W + (size_t)((c + 1) * KT + wk) * Dd + n0 + wc * 4;
            w0 = *(const float4*)Wp;
            w1 = *(const float4*)(Wp + 8 * Dd);
        }

        // compute on buf cur
        const float* Asb = As + cur * (KT * 128);
        const float* Wsb = Ws + cur * (KT * 128);
#pragma unroll
        for (int kk = 0; kk < KT; kk++) {
            const float* Ak = Asb + kk * 128;
            const float* Wr = Wsb + kk * 128;
            u64 ap[4];
            ap[0] = *(const u64*)&Ak[ty * 4];
            ap[1] = *(const u64*)&Ak[ty * 4 + 2];
            ap[2] = *(const u64*)&Ak[64 + ty * 4];
            ap[3] = *(const u64*)&Ak[64 + ty * 4 + 2];
            float4 bv0 = *(const float4*)&Wr[tx * 4];
            float4 bv1 = *(const float4*)&Wr[64 + tx * 4];
            u64 bd[8];
            bd[0] = pk2(bv0.x, bv0.x); bd[1] = pk2(bv0.y, bv0.y);
            bd[2] = pk2(bv0.z, bv0.z); bd[3] = pk2(bv0.w, bv0.w);
            bd[4] = pk2(bv1.x, bv1.x); bd[5] = pk2(bv1.y, bv1.y);
            bd[6] = pk2(bv1.z, bv1.z); bd[7] = pk2(bv1.w, bv1.w);
#pragma unroll
            for (int i = 0; i < 4; i++)
#pragma unroll
                for (int j = 0; j < 8; j++) ffma2(c2[i][j], ap[i], bd[j]);
        }

        if (has_next) {   // store chunk c+1 into other buffer
            float* Asn = As + (cur ^ 1) * (KT * 128);
            float* Wsn = Ws + (cur ^ 1) * (KT * 128);
            Asn[(ah * 8 + 0) * 128 + ar] = a0.x; Asn[(ah * 8 + 1) * 128 + ar] = a0.y;
            Asn[(ah * 8 + 2) * 128 + ar] = a0.z; Asn[(ah * 8 + 3) * 128 + ar] = a0.w;
            Asn[(ah * 8 + 4) * 128 + ar] = a1.x; Asn[(ah * 8 + 5) * 128 + ar] = a1.y;
            Asn[(ah * 8 + 6) * 128 + ar] = a1.z; Asn[(ah * 8 + 7) * 128 + ar] = a1.w;
            *(float4*)&Wsn[wk * 128 + wc * 4]       = w0;
            *(float4*)&Wsn[(wk + 8) * 128 + wc * 4] = w1;
        }
        __syncthreads();
    }

    // epilogue
#pragma unroll
    for (int i = 0; i < 4; i++) {
        int rbase = m0 + ((i < 2) ? (ty * 4 + i * 2) : (64 + ty * 4 + (i - 2) * 2));
#pragma unroll
        for (int j = 0; j < 8; j++) {
            int cidx = n0 + ((j < 4) ? (tx * 4 + j) : (64 + tx * 4 + (j - 4)));
            float2 f = upk2(c2[i][j]);
            float bia = bias[cidx];
            f.x += bia; f.y += bia;
#pragma unroll
            for (int s = 0; s < 2; s++) {
                int r = rbase + s;
                if (r >= Mrows) continue;
                float v = s ? f.y : f.x;
                int bi = r / Tt, t = r - (r / Tt) * Tt;
                int h = cidx >> 6, dk = cidx & 63;
                out[(((size_t)(bi * Hh + h)) * Tt + t) * DKk + dk] = v;
            }
        }
    }
}

__global__ void __launch_bounds__(256, 2) qk_kernel(
    const float* __restrict__ x,
    const float* __restrict__ Wq, const float* __restrict__ Wk2,
    const float* __restrict__ bq, const float* __restrict__ bk2,
    float* __restrict__ q, float* __restrict__ k)
{
    __shared__ float As[2 * KT * 128];
    __shared__ float Ws[2 * KT * 128];
    int z = blockIdx.z;
    gemm_core(x, z ? Wk2 : Wq, z ? bk2 : bq, z ? k : q, As, Ws);
}

// ---------------------------------------------------------------------------
// 2-limb 3-product BF16 GEMM (V, O) — double-buffered.
// CTA 128x128, 128 threads, warp tile 64x64, m16n8k16.
// Rows [h 16 | m 16 | pad 8] bf16, stride 40 b16 = 80 B. Buffer = 20480 B.
// ---------------------------------------------------------------------------
#define RB 40
#define BUFB 20480u
#define GEMM_SMEM_BF (2 * 20480)

union Pack8 { __nv_bfloat16 b[8]; uint4 u; };

__device__ __forceinline__ void bf16_store_tile(
    __nv_bfloat16* smb, int buf, int tid, const float4* pa, const float* pw)
{
    __nv_bfloat16* As = smb + buf * (BUFB / 2);       // in bf16 units: 10240
    __nv_bfloat16* Ws = As + 128 * RB;
    // A limbs: row tid
    {
        float vv[16];
#pragma unroll
        for (int i = 0; i < 4; i++) {
            vv[i * 4 + 0] = pa[i].x; vv[i * 4 + 1] = pa[i].y;
            vv[i * 4 + 2] = pa[i].z; vv[i * 4 + 3] = pa[i].w;
        }
        Pack8 h0, h1, m0p, m1p;
#pragma unroll
        for (int j = 0; j < 16; j++) {
            __nv_bfloat16 hb = __float2bfloat16_rn(vv[j]);
            __nv_bfloat16 mb = __float2bfloat16_rn(vv[j] - __bfloat162float(hb));
            if (j < 8) { h0.b[j] = hb; m0p.b[j] = mb; }
            else       { h1.b[j - 8] = hb; m1p.b[j - 8] = mb; }
        }
        __nv_bfloat16* Arow = As + tid * RB;
        *(uint4*)(Arow)      = h0.u;  *(uint4*)(Arow + 8)  = h1.u;
        *(uint4*)(Arow + 16) = m0p.u; *(uint4*)(Arow + 24) = m1p.u;
    }
    // W limbs: n-column tid
    {
        Pack8 h0, h1, m0p, m1p;
#pragma unroll
        for (int j = 0; j < 16; j++) {
            __nv_bfloat16 hb = __float2bfloat16_rn(pw[j]);
            __nv_bfloat16 mb = __float2bfloat16_rn(pw[j] - __bfloat162float(hb));
            if (j < 8) { h0.b[j] = hb; m0p.b[j] = mb; }
            else       { h1.b[j - 8] = hb; m1p.b[j - 8] = mb; }
        }
        __nv_bfloat16* Wrow = Ws + tid * RB;
        *(uint4*)(Wrow)      = h0.u;  *(uint4*)(Wrow + 8)  = h1.u;
        *(uint4*)(Wrow + 16) = m0p.u; *(uint4*)(Wrow + 24) = m1p.u;
    }
}

__global__ void __launch_bounds__(128, 2) bf16_gemm_kernel(
    const float* __restrict__ A, const float* __restrict__ W,
    const float* __restrict__ bias, float* __restrict__ out, int mode)
{
    extern __shared__ __nv_bfloat16 smb[];
    const uint32_t base_u = smem_u32(smb);

    const int tid  = threadIdx.x;
    const int lane = tid & 31;
    const int wid  = tid >> 5;
    const int wm   = wid >> 1;
    const int wn   = wid & 1;
    const int m0   = blockIdx.y * 128;
    const int n0   = blockIdx.x * 128;
    const bool arow_ok = (m0 + tid < Mrows);

    float d[4][8][4];
#pragma unroll
    for (int mf = 0; mf < 4; mf++)
#pragma unroll
        for (int nf = 0; nf < 8; nf++)
#pragma unroll
            for (int i = 0; i < 4; i++) d[mf][nf][i] = 0.f;

    const uint32_t a_off = (uint32_t)(wm * 64 + (lane & 15)) * 80u + ((lane >> 4) << 4);
    const uint32_t b_off = 10240u + (uint32_t)(wn * 64 + ((lane >> 4) << 3) + (lane & 7)) * 80u
                         + (((lane >> 3) & 1) << 4);

    float4 pa[4];
    float  pw[16];

    {   // chunk 0: LDG + split/store into buf0
        if (arow_ok) {
            const float* Ap = A + (size_t)(m0 + tid) * Dd;
#pragma unroll
            for (int i = 0; i < 4; i++) pa[i] = *(const float4*)(Ap + i * 4);
        } else {
#pragma unroll
            for (int i = 0; i < 4; i++) pa[i] = make_float4(0.f, 0.f, 0.f, 0.f);
        }
#pragma unroll
        for (int kq = 0; kq < 16; kq++)
            pw[kq] = W[(size_t)kq * Dd + n0 + tid];
        bf16_store_tile(smb, 0, tid, pa, pw);
    }
    __syncthreads();

    for (int c = 0; c < NCH; c++) {
        const int cur = c & 1;
        const bool has_next = (c + 1 < NCH);

        if (has_next) {   // LDG chunk c+1
            if (arow_ok) {
                const float* Ap = A + (size_t)(m0 + tid) * Dd + (c + 1) * 16;
#pragma unroll
                for (int i = 0; i < 4; i++) pa[i] = *(const float4*)(Ap + i * 4);
            } else {
#pragma unroll
                for (int i = 0; i < 4; i++) pa[i] = make_float4(0.f, 0.f, 0.f, 0.f);
            }
#pragma unroll
            for (int kq = 0; kq < 16; kq++)
                pw[kq] = W[(size_t)((c + 1) * 16 + kq) * Dd + n0 + tid];
        }

        // compute on buf cur: one k16 step, 3 products
        const uint32_t a_base = base_u + cur * BUFB + a_off;
        const uint32_t b_base = base_u + cur * BUFB + b_off;
        uint32_t ah[4][4], am[4][4], bh[4][4], bm[4][4];
#pragma unroll
        for (int mf = 0; mf < 4; mf++) ldsm4(ah[mf], a_base + mf * 1280u);
#pragma unroll
        for (int g = 0; g < 4; g++)    ldsm4(bh[g], b_base + g * 1280u);
#pragma unroll
        for (int mf = 0; mf < 4; mf++)
#pragma unroll
            for (int nf = 0; nf < 8; nf++)
                mma16(d[mf][nf], ah[mf], bh[nf >> 1][(nf & 1) * 2], bh[nf >> 1][(nf & 1) * 2 + 1]);
#pragma unroll
        for (int g = 0; g < 4; g++)    ldsm4(bm[g], b_base + g * 1280u + 32u);
#pragma unroll
        for (int mf = 0; mf < 4; mf++)
#pragma unroll
            for (int nf = 0; nf < 8; nf++)
                mma16(d[mf][nf], ah[mf], bm[nf >> 1][(nf & 1) * 2], bm[nf >> 1][(nf & 1) * 2 + 1]);
#pragma unroll
        for (int mf = 0; mf < 4; mf++) ldsm4(am[mf], a_base + mf * 1280u + 32u);
#pragma unroll
        for (int mf = 0; mf < 4; mf++)
#pragma unroll
            for (int nf = 0; nf < 8; nf++)
                mma16(d[mf][nf], am[mf], bh[nf >> 1][(nf & 1) * 2], bh[nf >> 1][(nf & 1) * 2 + 1]);

        if (has_next)
            bf16_store_tile(smb, cur ^ 1, tid, pa, pw);
        __syncthreads();
    }

    // epilogue
    const int gid = lane >> 2, tig = lane & 3;
#pragma unroll
    for (int mf = 0; mf < 4; mf++) {
        const int r0 = m0 + wm * 64 + mf * 16 + gid;
        const int r1 = r0 + 8;
        int bi0 = 0, t0 = 0, bi1 = 0, t1 = 0;
        const bool v0 = (r0 < Mrows), v1 = (r1 < Mrows);
        if (v0) { bi0 = r0 / Tt; t0 = r0 - bi0 * Tt; }
        if (v1) { bi1 = r1 / Tt; t1 = r1 - bi1 * Tt; }
#pragma unroll
        for (int nf = 0; nf < 8; nf++) {
            const int cg = n0 + wn * 64 + nf * 8 + tig * 2;
            const float bx = bias[cg], by = bias[cg + 1];
            float2 o0 = make_float2(d[mf][nf][0] + bx, d[mf][nf][1] + by);
            float2 o1 = make_float2(d[mf][nf][2] + bx, d[mf][nf][3] + by);
            if (mode == 0) {
                const int h = cg >> 6, dk = cg & 63;
                if (v0) *(float2*)&out[(((size_t)(bi0 * Hh + h)) * Tt + t0) * DKk + dk] = o0;
                if (v1) *(float2*)&out[(((size_t)(bi1 * Hh + h)) * Tt + t1) * DKk + dk] = o1;
            } else {
                if (v0) *(float2*)&out[(size_t)r0 * Dd + cg] = o0;
                if (v1) *(float2*)&out[(size_t)r1 * Dd + cg] = o1;
            }
        }
    }
}

// ---------------------------------------------------------------------------
// Attention (unchanged): per (b,h) CTA, 16 warps, 4 rows/warp, rotated smem.
// ---------------------------------------------------------------------------
#define NW 16
#define ATTN_SMEM ((2 * Tt * 64 + NW * 800) * 4)

__global__ void __launch_bounds__(32 * NW) attn3_kernel(
    const float* __restrict__ Q, const float* __restrict__ K,
    const float* __restrict__ V, float* __restrict__ ctx)
{
    extern __shared__ float sm[];
    float* Ks = sm;
    float* Vs = sm + Tt * 64;
    const int tid  = threadIdx.x;
    const int lane = tid & 31;
    const int w    = tid >> 5;
    float* Pg = sm + 2 * Tt * 64 + w * 800;

    const int bh = blockIdx.x;
    const int b  = bh / Hh;
    const int h  = bh - b * Hh;

    const float* Kb = K + (size_t)bh * Tt * DKk;
    const float* Vb = V + (size_t)bh * Tt * DKk;
    const float* Qb = Q + (size_t)bh * Tt * DKk;

    for (int e = tid; e < Tt * 32; e += 32 * NW) {
        int j = e >> 5, p = e & 31, c = 2 * p;
        int off = j * 64 + ((c + 2 * j) & 63);
        *(float2*)&Ks[off] = *(const float2*)&Kb[j * 64 + c];
        *(float2*)&Vs[off] = *(const float2*)&Vb[j * 64 + c];
    }
    __syncthreads();

    int jj[7], rot[7];
#pragma unroll
    for (int u = 0; u < 7; u++) {
        int j = lane + 32 * u;
        jj[u]  = (j > Tt - 1) ? (Tt - 1) : j;
        rot[u] = (2 * jj[u]) & 63;
    }
    const int myc = 2 * lane;

    for (int g = w; g < 50; g += NW) {
        const int r0 = g * 4;
        int rs[4];
#pragma unroll
        for (int s = 0; s < 4; s++) rs[s] = (r0 + s > Tt - 1) ? (Tt - 1) : (r0 + s);

        u64 acc[4][7];
#pragma unroll
        for (int s = 0; s < 4; s++)
#pragma unroll
            for (int u = 0; u < 7; u++) acc[s][u] = 0ull;

#pragma unroll
        for (int dc = 0; dc < 8; dc++) {
            u64 qp[4][4];
#pragma unroll
            for (int s = 0; s < 4; s++) {
                const float* qs = Qb + rs[s] * DKk + dc * 8;
                float4 qa = *(const float4*)qs;
                float4 qb = *(const float4*)(qs + 4);
                qp[s][0] = pk2(qa.x, qa.y); qp[s][1] = pk2(qa.z, qa.w);
                qp[s][2] = pk2(qb.x, qb.y); qp[s][3] = pk2(qb.z, qb.w);
            }
            const int c0 = dc * 8;
#pragma unroll
            for (int u = 0; u < 7; u++) {
                const float* kr = Ks + jj[u] * 64;
                u64 kp0 = *(const u64*)&kr[(c0 + 0 + rot[u]) & 63];
                u64 kp1 = *(const u64*)&kr[(c0 + 2 + rot[u]) & 63];
                u64 kp2 = *(const u64*)&kr[(c0 + 4 + rot[u]) & 63];
                u64 kp3 = *(const u64*)&kr[(c0 + 6 + rot[u]) & 63];
#pragma unroll
                for (int s = 0; s < 4; s++) {
                    ffma2(acc[s][u], qp[s][0], kp0);
                    ffma2(acc[s][u], qp[s][1], kp1);
                    ffma2(acc[s][u], qp[s][2], kp2);
                    ffma2(acc[s][u], qp[s][3], kp3);
                }
            }
        }

        float iv[4];
#pragma unroll
        for (int s = 0; s < 4; s++) {
            float sc[7];
            float mx = -1e30f;
#pragma unroll
            for (int u = 0; u < 7; u++) {
                float2 f = upk2(acc[s][u]);
                float val = floorf((f.x + f.y) * 0.125f);
                sc[u] = (lane + 32 * u < Tt) ? val : -1e30f;
                mx = fmaxf(mx, sc[u]);
            }
#pragma unroll
            for (int o = 16; o; o >>= 1) mx = fmaxf(mx, __shfl_xor_sync(0xffffffffu, mx, o));
            float sum = 0.f;
#pragma unroll
            for (int u = 0; u < 7; u++) {
                if (lane + 32 * u < Tt) {
                    float p = __expf(sc[u] - mx);
                    Pg[jj[u] * 4 + s] = p;
                    sum += p;
                }
            }
#pragma unroll
            for (int o = 16; o; o >>= 1) sum += __shfl_xor_sync(0xffffffffu, sum, o);
            iv[s] = 1.f / sum;
        }
        __syncwarp();

        u64 a[4] = {0ull, 0ull, 0ull, 0ull};
        for (int j = 0; j < Tt - 1; j += 2) {
            u64 v0 = *(const u64*)&Vs[j * 64 + ((myc + 2 * j) & 63)];
            u64 v1 = *(const u64*)&Vs[(j + 1) * 64 + ((myc + 2 * j + 2) & 63)];
            float4 pa = *(const float4*)&Pg[j * 4];
            float4 pb = *(const float4*)&Pg[j * 4 + 4];
            ffma2(a[0], pk2(pa.x, pa.x), v0); ffma2(a[0], pk2(pb.x, pb.x), v1);
            ffma2(a[1], pk2(pa.y, pa.y), v0); ffma2(a[1], pk2(pb.y, pb.y), v1);
            ffma2(a[2], pk2(pa.z, pa.z), v0); ffma2(a[2], pk2(pb.z, pb.z), v1);
            ffma2(a[3], pk2(pa.w, pa.w), v0); ffma2(a[3], pk2(pb.w, pb.w), v1);
        }
        {
            int j = Tt - 1;
            u64 v0 = *(const u64*)&Vs[j * 64 + ((myc + 2 * j) & 63)];
            float4 pa = *(const float4*)&Pg[j * 4];
            ffma2(a[0], pk2(pa.x, pa.x), v0);
            ffma2(a[1], pk2(pa.y, pa.y), v0);
            ffma2(a[2], pk2(pa.z, pa.z), v0);
            ffma2(a[3], pk2(pa.w, pa.w), v0);
        }

#pragma unroll
        for (int s = 0; s < 4; s++) {
            float2 o = upk2(a[s]);
            o.x *= iv[s]; o.y *= iv[s];
            *(float2*)&ctx[((size_t)(b * Tt + rs[s])) * Dd + h * DKk + myc] = o;
        }
        __syncwarp();
    }
}

// ---------------------------------------------------------------------------
extern "C" void kernel_launch(void* const* d_in, const int* in_sizes, int n_in,
                              void* d_out, int out_size)
{
    const float* x  = (const float*)d_in[0];
    const float* Wq = (const float*)d_in[1];
    const float* bq = (const float*)d_in[2];
    const float* Wk = (const float*)d_in[3];
    const float* bk = (const float*)d_in[4];
    const float* Wv = (const float*)d_in[5];
    const float* bv = (const float*)d_in[6];
    const float* Wo = (const float*)d_in[7];
    const float* bo = (const float*)d_in[8];
    float* out = (float*)d_out;

    float *q, *k, *v, *ctx;
    cudaGetSymbolAddress((void**)&q,   g_q);
    cudaGetSymbolAddress((void**)&k,   g_k);
    cudaGetSymbolAddress((void**)&v,   g_v);
    cudaGetSymbolAddress((void**)&ctx, g_ctx);

    cudaFuncSetAttribute(bf16_gemm_kernel,
                         cudaFuncAttributeMaxDynamicSharedMemorySize, GEMM_SMEM_BF);
    cudaFuncSetAttribute(attn3_kernel,
                         cudaFuncAttributeMaxDynamicSharedMemorySize, ATTN_SMEM);

    // Q, K: exact fp32 FFMA2 (floor-sensitive path)
    dim3 gqk(Dd / 128, (Mrows + 127) / 128, 2);   // 6 x 99 x 2
    qk_kernel<<<gqk, 256>>>(x, Wq, Wk, bq, bk, q, k);

    // V: bf16 2-limb 3-product (smooth path)
    dim3 gbf(Dd / 128, (Mrows + 127) / 128);      // 6 x 99
    bf16_gemm_kernel<<<gbf, 128, GEMM_SMEM_BF>>>(x, Wv, bv, v, 0);

    attn3_kernel<<<Bc * Hh, 32 * NW, ATTN_SMEM>>>(q, k, v, ctx);

    // O: bf16 2-limb 3-product
    bf16_gemm_kernel<<<gbf, 128, GEMM_SMEM_BF>>>(ctx, Wo, bo, out, 1);
}